// round 14
// baseline (speedup 1.0000x reference)
#include <cuda_runtime.h>
#include <cuda_bf16.h>
#include <cuda_fp16.h>
#include <stdint.h>
#include <math.h>

// Problem constants (fixed by the dataset)
#define NN 100000      // nodes
#define NE 1600000     // edges
#define NH 4           // heads
#define NEG_SLOPE 0.2f
#define NB 391         // ceil(NN/256)
#define NTILES 782     // ceil(NN/128)
#define NCTA 148       // persistent CTAs (1 per SM)

// ---------------- device scratch ----------------
__device__ __align__(16) __half g_xh[NN * 128];  // projected features, fp16
__device__ float g_as[NN * NH];         // per-node src logits (fp32)
__device__ float g_ad[NN * NH];         // per-node dst logits (fp32)
__device__ int   g_cnt[NN];
__device__ int   g_rowptr[NN];
__device__ int   g_cursor[NN];
__device__ int   g_total;
__device__ int   g_csr_src[NE];
// padded-transposed bf16 weights: [hi | lo], each [256 n][136 k] (stride 272 B)
__device__ __align__(16) __nv_bfloat16 g_Bpk[2 * 256 * 136];
// pre-split bf16 A (feat): [NN][128] each
__device__ __align__(16) __nv_bfloat16 g_Ahi[NN * 128];
__device__ __align__(16) __nv_bfloat16 g_Alo[NN * 128];

__device__ __forceinline__ float lrelu(float v) {
    return v > 0.0f ? v : NEG_SLOPE * v;
}

__device__ __forceinline__ uint32_t smem_u32(const void* p) {
    uint32_t a;
    asm("{ .reg .u64 t; cvta.to.shared.u64 t, %1; cvt.u32.u64 %0, t; }" : "=r"(a) : "l"(p));
    return a;
}

#define CP_ASYNC16(saddr, gptr)                                                \
    asm volatile("cp.async.cg.shared.global [%0], [%1], 16;"                   \
                 :: "r"(saddr), "l"(gptr))
#define CP_COMMIT() asm volatile("cp.async.commit_group;" ::: "memory")
#define CP_WAIT0()  asm volatile("cp.async.wait_group 0;" ::: "memory")

#define LDSM4(r0, r1, r2, r3, addr)                                            \
    asm volatile("ldmatrix.sync.aligned.m8n8.x4.shared.b16 {%0,%1,%2,%3}, [%4];" \
                 : "=r"(r0), "=r"(r1), "=r"(r2), "=r"(r3) : "r"(addr))

#define MMA16816(c, a, b)                                                      \
    asm volatile(                                                              \
        "mma.sync.aligned.m16n8k16.row.col.f32.bf16.bf16.f32 "                 \
        "{%0,%1,%2,%3}, {%4,%5,%6,%7}, {%8,%9}, {%0,%1,%2,%3};"                \
        : "+f"((c)[0]), "+f"((c)[1]), "+f"((c)[2]), "+f"((c)[3])               \
        : "r"((a)[0]), "r"((a)[1]), "r"((a)[2]), "r"((a)[3]),                  \
          "r"((b)[0]), "r"((b)[1]))

// ---------------- prep: weights + feat -> split bf16 ----------------
__global__ void prep_ab(const float* __restrict__ W, const float* __restrict__ Wres,
                        const float* __restrict__ feat) {
    int b = blockIdx.x;
    int tid = threadIdx.x;
    if (b < 16) {
        int t = b * 256 + tid;          // < 4096
        int n  = t >> 4;
        int kg = (t & 15) * 8;
        const float* Wm = (n < 128) ? W : Wres;
        int col = n & 127;
        unsigned short hi[8], lo[8];
#pragma unroll
        for (int i = 0; i < 8; i++) {
            float a = Wm[(size_t)(kg + i) * 128 + col];
            __nv_bfloat16 h = __float2bfloat16(a);
            __nv_bfloat16 l = __float2bfloat16(a - __bfloat162float(h));
            hi[i] = *(unsigned short*)&h;
            lo[i] = *(unsigned short*)&l;
        }
        *(uint4*)(g_Bpk + (size_t)n * 136 + kg)             = *(uint4*)hi;
        *(uint4*)(g_Bpk + 256 * 136 + (size_t)n * 136 + kg) = *(uint4*)lo;
    } else {
        int i = (b - 16) * 256 + tid;
        if (i >= NN * 16) return;
        int row = i >> 4;
        int kg = (i & 15) * 8;
        float4 v0 = *(const float4*)(feat + (size_t)row * 128 + kg);
        float4 v1 = *(const float4*)(feat + (size_t)row * 128 + kg + 4);
        float a[8] = {v0.x, v0.y, v0.z, v0.w, v1.x, v1.y, v1.z, v1.w};
        unsigned short hi[8], lo[8];
#pragma unroll
        for (int q = 0; q < 8; q++) {
            __nv_bfloat16 h = __float2bfloat16(a[q]);
            __nv_bfloat16 l = __float2bfloat16(a[q] - __bfloat162float(h));
            hi[q] = *(unsigned short*)&h;
            lo[q] = *(unsigned short*)&l;
        }
        *(uint4*)(g_Ahi + (size_t)row * 128 + kg) = *(uint4*)hi;
        *(uint4*)(g_Alo + (size_t)row * 128 + kg) = *(uint4*)lo;
    }
}

// ---------------- persistent tensor-core dual GEMM ----------------
// 148 CTAs x 512 threads. B (hi|lo, 139264 B) resident in SMEM.
// A streamed in k-chunks of 64 with hi+lo together (36864 B slots, 2 slots).
// Per tile: 2 iterations; each = wait + 1 sync + prefetch + 12 k-steps
// (3 passes x 4 k-steps) accumulating in registers.
#define SM_B    0u
#define SM_A    139264u
#define A_SLOT  36864u
#define A_HALF  18432u
#define GEMM_SMEM 212992

// fetch one A chunk (rows row0..row0+127, k-half ch) hi+lo into slot
__device__ __forceinline__ void fetch_chunk(uint32_t sbase, int row0, int ch,
                                            int slot, int tid) {
    const uint32_t sb = sbase + SM_A + (uint32_t)slot * A_SLOT;
#pragma unroll
    for (int j = 0; j < 2; j++) {
        int i = tid + j * 512;          // 1024 16B chunks per half
        int r = i >> 3;                 // 8 chunks per 128B row
        int q = i & 7;
        int gr = row0 + r;
        if (gr >= NN) gr = NN - 1;      // clamped rows discarded in epilogue
        size_t goff = (size_t)gr * 256 + ch * 128 + q * 16;
        uint32_t soff = (uint32_t)(r * 144 + q * 16);
        CP_ASYNC16(sb + soff,          (const char*)g_Ahi + goff);
        CP_ASYNC16(sb + A_HALF + soff, (const char*)g_Alo + goff);
    }
}

__global__ void __launch_bounds__(512, 1)
gemm_tc(const float* __restrict__ att_src,
        const float* __restrict__ att_dst,
        float* __restrict__ out)
{
    extern __shared__ unsigned char smem[];
    const uint32_t sbase = smem_u32(smem);
    const int tid = threadIdx.x;

    // ---- load resident B once: 139264 B = 8704 x 16B, 17 per thread ----
    {
        const char* bs = (const char*)g_Bpk;
#pragma unroll
        for (int j = 0; j < 17; j++) {
            uint32_t off = (uint32_t)(tid + j * 512) * 16;
            CP_ASYNC16(sbase + SM_B + off, bs + off);
        }
    }

    const int lane = tid & 31;
    const int wid = tid >> 5;
    const int wm = wid & 3;        // 4 m-tiles of 32 rows
    const int wn = wid >> 2;       // 4 n-tiles of 64 cols

    const uint32_t aRow = (uint32_t)(wm * 32 + (lane & 15));
    const uint32_t aKb  = (uint32_t)((lane >> 4) * 16);
    const uint32_t bN   = (uint32_t)(wn * 64 + ((lane >> 4) * 8) + (lane & 7));
    const uint32_t bKb  = (uint32_t)(((lane >> 3) & 1) * 16);
    const int qlane = lane >> 2;
    const int qcol  = (lane & 3) * 2;

    // prologue: first chunk (shares the commit group with the B load)
    int tile = blockIdx.x;
    if (tile < NTILES) fetch_chunk(sbase, tile * 128, 0, 0, tid);
    CP_COMMIT();

    int slot = 0;
    for (; tile < NTILES; tile += NCTA) {
        const int row0 = tile * 128;

        float c[2][8][4];
#pragma unroll
        for (int mi = 0; mi < 2; mi++)
#pragma unroll
            for (int ni = 0; ni < 8; ni++)
#pragma unroll
                for (int q = 0; q < 4; q++) c[mi][ni][q] = 0.f;

#pragma unroll
        for (int ch = 0; ch < 2; ch++) {
            CP_WAIT0();            // own fetch of current chunk complete
            __syncthreads();       // everyone's fetch visible; prev compute retired

            // prefetch the next chunk into the slot freed by the prev iteration
            {
                int ntile = (ch == 0) ? tile : tile + NCTA;
                int nch = ch ^ 1;
                if (ntile < NTILES)
                    fetch_chunk(sbase, ntile * 128, nch, slot ^ 1, tid);
                CP_COMMIT();
            }

            // 3 passes x 4 k-steps on this chunk
#pragma unroll
            for (int p = 0; p < 3; p++) {
                const uint32_t aAddr0 = sbase + SM_A + (uint32_t)slot * A_SLOT +
                                        (p == 2 ? A_HALF : 0u) + aRow * 144 + aKb;
                const uint32_t bAddr0 = sbase + SM_B + (p == 1 ? 69632u : 0u) +
                                        bN * 272 + (uint32_t)(ch * 128) + bKb;
#pragma unroll
                for (int ks = 0; ks < 4; ks++) {
                    const uint32_t kb = (uint32_t)(ks * 32);
                    uint32_t a[2][4];
                    LDSM4(a[0][0], a[0][1], a[0][2], a[0][3], aAddr0 + kb);
                    LDSM4(a[1][0], a[1][1], a[1][2], a[1][3], aAddr0 + 16 * 144 + kb);
                    uint32_t b[8][2];
#pragma unroll
                    for (int nj = 0; nj < 4; nj++) {
                        LDSM4(b[2 * nj][0], b[2 * nj][1], b[2 * nj + 1][0], b[2 * nj + 1][1],
                              bAddr0 + (uint32_t)(nj * 16 * 272) + kb);
                    }
#pragma unroll
                    for (int mi = 0; mi < 2; mi++)
#pragma unroll
                        for (int ni = 0; ni < 8; ni++)
                            MMA16816(c[mi][ni], a[mi], b[ni]);
                }
            }
            slot ^= 1;
        }

        // ---- epilogue (registers only; no SMEM hazard) ----
#pragma unroll
        for (int mi = 0; mi < 2; mi++) {
            const int rA = row0 + wm * 32 + mi * 16 + qlane;
            const int rB = rA + 8;
#pragma unroll
            for (int ni = 0; ni < 8; ni++) {
                const int col = wn * 64 + ni * 8 + qcol;
                if (col < 128) {
                    __half2 pA = __float22half2_rn(make_float2(c[mi][ni][0], c[mi][ni][1]));
                    __half2 pB = __float22half2_rn(make_float2(c[mi][ni][2], c[mi][ni][3]));
                    if (rA < NN) *(__half2*)(g_xh + (size_t)rA * 128 + col) = pA;
                    if (rB < NN) *(__half2*)(g_xh + (size_t)rB * 128 + col) = pB;
                } else {
                    if (rA < NN) *(float2*)(out + (size_t)rA * 128 + col - 128) =
                        make_float2(c[mi][ni][0], c[mi][ni][1]);
                    if (rB < NN) *(float2*)(out + (size_t)rB * 128 + col - 128) =
                        make_float2(c[mi][ni][2], c[mi][ni][3]);
                }
            }
        }

        // fused attention logits for the x half (wn 0,1), fp32-exact
        if (wn < 2) {
            const int hA = wn * 2;
            const int hB = wn * 2 + 1;
#pragma unroll
            for (int mi = 0; mi < 2; mi++) {
#pragma unroll
                for (int rp = 0; rp < 2; rp++) {
                    float sa = 0.f, da = 0.f, sb = 0.f, db = 0.f;
#pragma unroll
                    for (int ni = 0; ni < 4; ni++) {
                        const int col = wn * 64 + ni * 8 + qcol;
                        float x0 = c[mi][ni][2 * rp], x1 = c[mi][ni][2 * rp + 1];
                        sa = fmaf(x0, __ldg(att_src + col), sa);
                        sa = fmaf(x1, __ldg(att_src + col + 1), sa);
                        da = fmaf(x0, __ldg(att_dst + col), da);
                        da = fmaf(x1, __ldg(att_dst + col + 1), da);
                    }
#pragma unroll
                    for (int ni = 4; ni < 8; ni++) {
                        const int col = wn * 64 + ni * 8 + qcol;
                        float x0 = c[mi][ni][2 * rp], x1 = c[mi][ni][2 * rp + 1];
                        sb = fmaf(x0, __ldg(att_src + col), sb);
                        sb = fmaf(x1, __ldg(att_src + col + 1), sb);
                        db = fmaf(x0, __ldg(att_dst + col), db);
                        db = fmaf(x1, __ldg(att_dst + col + 1), db);
                    }
                    sa += __shfl_xor_sync(0xffffffffu, sa, 1);
                    sa += __shfl_xor_sync(0xffffffffu, sa, 2);
                    da += __shfl_xor_sync(0xffffffffu, da, 1);
                    da += __shfl_xor_sync(0xffffffffu, da, 2);
                    sb += __shfl_xor_sync(0xffffffffu, sb, 1);
                    sb += __shfl_xor_sync(0xffffffffu, sb, 2);
                    db += __shfl_xor_sync(0xffffffffu, db, 1);
                    db += __shfl_xor_sync(0xffffffffu, db, 2);
                    if ((lane & 3) == 0) {
                        const int r = row0 + wm * 32 + mi * 16 + rp * 8 + qlane;
                        if (r < NN) {
                            g_as[r * NH + hA] = sa;
                            g_ad[r * NH + hA] = da;
                            g_as[r * NH + hB] = sb;
                            g_ad[r * NH + hB] = db;
                        }
                    }
                }
            }
        }
    }
}

// ---------------- CSR build ----------------
__global__ void zero_cnt_kernel() {
    int i = blockIdx.x * blockDim.x + threadIdx.x;
    if (i < NN) g_cnt[i] = 0;
    if (i == 0) g_total = 0;
}

__global__ void hist_kernel(const int* __restrict__ dst) {
    int e = blockIdx.x * blockDim.x + threadIdx.x;
    if (e < NE) atomicAdd(&g_cnt[dst[e]], 1);
}

__global__ void alloc_kernel() {
    int i = blockIdx.x * blockDim.x + threadIdx.x;
    if (i >= NN) return;
    int c = g_cnt[i];
    int r = atomicAdd(&g_total, c);
    g_rowptr[i] = r;
    g_cursor[i] = r;
}

__global__ void scatter_kernel(const int* __restrict__ src,
                               const int* __restrict__ dst) {
    int e = blockIdx.x * blockDim.x + threadIdx.x;
    if (e >= NE) return;
    int d = dst[e];
    int pos = atomicAdd(&g_cursor[d], 1);
    g_csr_src[pos] = src[e];
}

// ---------------- node aggregation: half-warp per edge, 2-wide, single pass ----------------
__global__ void __launch_bounds__(256)
node_agg_kernel(float* __restrict__ out)
{
    int d = (blockIdx.x * blockDim.x + threadIdx.x) >> 5;
    int lane = threadIdx.x & 31;
    if (d >= NN) return;
    const int n = g_cnt[d];
    if (n == 0) return;   // out already holds the residual
    const int base = g_rowptr[d];

    const int half = lane >> 4;
    const int l16  = lane & 15;
    const int h    = l16 >> 2;
    const float adh = g_ad[(size_t)d * NH + h];

    float acc[8];
#pragma unroll
    for (int q = 0; q < 8; q++) acc[q] = 0.f;
    float den = 0.f;

    const int* cs = g_csr_src + base;
    const __half* xb = g_xh + (size_t)l16 * 8;

    int i = half;
    for (; i + 2 < n; i += 4) {
        int s0 = cs[i], s1 = cs[i + 2];
        float a0 = g_as[(size_t)s0 * NH + h];
        float a1 = g_as[(size_t)s1 * NH + h];
        uint4 v0 = *(const uint4*)(xb + (size_t)s0 * 128);
        uint4 v1 = *(const uint4*)(xb + (size_t)s1 * 128);
        float p0 = __expf(lrelu(a0 + adh));
        float p1 = __expf(lrelu(a1 + adh));
        den += p0 + p1;
        const __half2* b0 = (const __half2*)&v0;
        const __half2* b1 = (const __half2*)&v1;
#pragma unroll
        for (int q = 0; q < 4; q++) {
            float2 f0 = __half22float2(b0[q]);
            float2 f1 = __half22float2(b1[q]);
            acc[2 * q]     = fmaf(f0.x, p0, acc[2 * q]);
            acc[2 * q + 1] = fmaf(f0.y, p0, acc[2 * q + 1]);
            acc[2 * q]     = fmaf(f1.x, p1, acc[2 * q]);
            acc[2 * q + 1] = fmaf(f1.y, p1, acc[2 * q + 1]);
        }
    }
    if (i < n) {
        int s0 = cs[i];
        float a0 = g_as[(size_t)s0 * NH + h];
        uint4 v0 = *(const uint4*)(xb + (size_t)s0 * 128);
        float p0 = __expf(lrelu(a0 + adh));
        den += p0;
        const __half2* b0 = (const __half2*)&v0;
#pragma unroll
        for (int q = 0; q < 4; q++) {
            float2 f0 = __half22float2(b0[q]);
            acc[2 * q]     = fmaf(f0.x, p0, acc[2 * q]);
            acc[2 * q + 1] = fmaf(f0.y, p0, acc[2 * q + 1]);
        }
    }

#pragma unroll
    for (int q = 0; q < 8; q++)
        acc[q] += __shfl_xor_sync(0xffffffffu, acc[q], 16);
    den += __shfl_xor_sync(0xffffffffu, den, 16);

    if (half == 0) {
        const float inv = 1.0f / den;
        float* o = out + (size_t)d * 128 + l16 * 8;
        float4 r0 = *(const float4*)o;
        float4 r1 = *(const float4*)(o + 4);
        r0.x = fmaf(acc[0], inv, r0.x);
        r0.y = fmaf(acc[1], inv, r0.y);
        r0.z = fmaf(acc[2], inv, r0.z);
        r0.w = fmaf(acc[3], inv, r0.w);
        r1.x = fmaf(acc[4], inv, r1.x);
        r1.y = fmaf(acc[5], inv, r1.y);
        r1.z = fmaf(acc[6], inv, r1.z);
        r1.w = fmaf(acc[7], inv, r1.w);
        *(float4*)o = r0;
        *(float4*)(o + 4) = r1;
    }
}

// ---------------- launch ----------------
extern "C" void kernel_launch(void* const* d_in, const int* in_sizes, int n_in,
                              void* d_out, int out_size)
{
    const float* feat    = (const float*)d_in[0];
    const float* W       = (const float*)d_in[1];
    const float* att_src = (const float*)d_in[2];
    const float* att_dst = (const float*)d_in[3];
    const float* Wres    = (const float*)d_in[4];
    const int*   src     = (const int*)d_in[5];
    const int*   dst     = (const int*)d_in[6];
    float* out = (float*)d_out;

    static cudaStream_t s2 = nullptr;
    static cudaEvent_t evFork = nullptr, evJoin = nullptr;
    if (!s2) {
        cudaFuncSetAttribute(gemm_tc,
                             cudaFuncAttributeMaxDynamicSharedMemorySize,
                             GEMM_SMEM);
        cudaStreamCreateWithFlags(&s2, cudaStreamNonBlocking);
        cudaEventCreateWithFlags(&evFork, cudaEventDisableTiming);
        cudaEventCreateWithFlags(&evJoin, cudaEventDisableTiming);
    }

    // fork: CSR build on s2, prep+GEMM on the main stream.
    // Enqueue order keeps gemm_tc 4th (profiler targeting).
    cudaEventRecord(evFork, 0);
    cudaStreamWaitEvent(s2, evFork, 0);

    zero_cnt_kernel<<<NB, 256, 0, s2>>>();                       // 1
    hist_kernel<<<(NE + 255) / 256, 256, 0, s2>>>(dst);          // 2
    prep_ab<<<16 + (NN * 16 + 255) / 256, 256>>>(W, Wres, feat); // 3
    gemm_tc<<<NCTA, 512, GEMM_SMEM>>>(att_src, att_dst, out);    // 4
    alloc_kernel<<<NB, 256, 0, s2>>>();                          // 5
    scatter_kernel<<<(NE + 255) / 256, 256, 0, s2>>>(src, dst);  // 6
    cudaEventRecord(evJoin, s2);

    // join: aggregation needs both GEMM outputs and the CSR
    cudaStreamWaitEvent(0, evJoin, 0);
    node_agg_kernel<<<(NN * 32 + 255) / 256, 256>>>(out);        // 7
}

// round 15
// speedup vs baseline: 1.1242x; 1.1242x over previous
#include <cuda_runtime.h>
#include <cuda_bf16.h>
#include <cuda_fp16.h>
#include <stdint.h>
#include <math.h>

// Problem constants (fixed by the dataset)
#define NN 100000      // nodes
#define NE 1600000     // edges
#define NH 4           // heads
#define NEG_SLOPE 0.2f
#define NB 391         // ceil(NN/256)
#define NTILES 782     // ceil(NN/128)
#define NCTA 148       // persistent CTAs (1 per SM)

// ---------------- device scratch ----------------
__device__ __align__(16) __half g_xh[NN * 128];  // projected features, fp16
__device__ float g_as[NN * NH];         // per-node src logits (fp32)
__device__ float g_ad[NN * NH];         // per-node dst logits (fp32)
__device__ int   g_cnt[NN];
__device__ int   g_rowptr[NN];
__device__ int   g_cursor[NN];
__device__ int   g_total;
__device__ int   g_csr_src[NE];
// padded-transposed bf16 weights: [hi | lo], each [256 n][136 k] (stride 272 B)
__device__ __align__(16) __nv_bfloat16 g_Bpk[2 * 256 * 136];
// pre-split bf16 A (feat): [NN][128] each
__device__ __align__(16) __nv_bfloat16 g_Ahi[NN * 128];
__device__ __align__(16) __nv_bfloat16 g_Alo[NN * 128];

__device__ __forceinline__ float lrelu(float v) {
    return v > 0.0f ? v : NEG_SLOPE * v;
}

__device__ __forceinline__ uint32_t smem_u32(const void* p) {
    uint32_t a;
    asm("{ .reg .u64 t; cvta.to.shared.u64 t, %1; cvt.u32.u64 %0, t; }" : "=r"(a) : "l"(p));
    return a;
}

#define CP_ASYNC16(saddr, gptr)                                                \
    asm volatile("cp.async.cg.shared.global [%0], [%1], 16;"                   \
                 :: "r"(saddr), "l"(gptr))
#define CP_COMMIT() asm volatile("cp.async.commit_group;" ::: "memory")
#define CP_WAIT1()  asm volatile("cp.async.wait_group 1;" ::: "memory")

#define LDSM4(r0, r1, r2, r3, addr)                                            \
    asm volatile("ldmatrix.sync.aligned.m8n8.x4.shared.b16 {%0,%1,%2,%3}, [%4];" \
                 : "=r"(r0), "=r"(r1), "=r"(r2), "=r"(r3) : "r"(addr))

#define MMA16816(c, a, b)                                                      \
    asm volatile(                                                              \
        "mma.sync.aligned.m16n8k16.row.col.f32.bf16.bf16.f32 "                 \
        "{%0,%1,%2,%3}, {%4,%5,%6,%7}, {%8,%9}, {%0,%1,%2,%3};"                \
        : "+f"((c)[0]), "+f"((c)[1]), "+f"((c)[2]), "+f"((c)[3])               \
        : "r"((a)[0]), "r"((a)[1]), "r"((a)[2]), "r"((a)[3]),                  \
          "r"((b)[0]), "r"((b)[1]))

// ---------------- prep: weights + feat -> split bf16 ----------------
__global__ void prep_ab(const float* __restrict__ W, const float* __restrict__ Wres,
                        const float* __restrict__ feat) {
    int b = blockIdx.x;
    int tid = threadIdx.x;
    if (b < 16) {
        int t = b * 256 + tid;          // < 4096
        int n  = t >> 4;
        int kg = (t & 15) * 8;
        const float* Wm = (n < 128) ? W : Wres;
        int col = n & 127;
        unsigned short hi[8], lo[8];
#pragma unroll
        for (int i = 0; i < 8; i++) {
            float a = Wm[(size_t)(kg + i) * 128 + col];
            __nv_bfloat16 h = __float2bfloat16(a);
            __nv_bfloat16 l = __float2bfloat16(a - __bfloat162float(h));
            hi[i] = *(unsigned short*)&h;
            lo[i] = *(unsigned short*)&l;
        }
        *(uint4*)(g_Bpk + (size_t)n * 136 + kg)             = *(uint4*)hi;
        *(uint4*)(g_Bpk + 256 * 136 + (size_t)n * 136 + kg) = *(uint4*)lo;
    } else {
        int i = (b - 16) * 256 + tid;
        if (i >= NN * 16) return;
        int row = i >> 4;
        int kg = (i & 15) * 8;
        float4 v0 = *(const float4*)(feat + (size_t)row * 128 + kg);
        float4 v1 = *(const float4*)(feat + (size_t)row * 128 + kg + 4);
        float a[8] = {v0.x, v0.y, v0.z, v0.w, v1.x, v1.y, v1.z, v1.w};
        unsigned short hi[8], lo[8];
#pragma unroll
        for (int q = 0; q < 8; q++) {
            __nv_bfloat16 h = __float2bfloat16(a[q]);
            __nv_bfloat16 l = __float2bfloat16(a[q] - __bfloat162float(h));
            hi[q] = *(unsigned short*)&h;
            lo[q] = *(unsigned short*)&l;
        }
        *(uint4*)(g_Ahi + (size_t)row * 128 + kg) = *(uint4*)hi;
        *(uint4*)(g_Alo + (size_t)row * 128 + kg) = *(uint4*)lo;
    }
}

// ---------------- persistent tensor-core dual GEMM ----------------
// 148 CTAs x 512 threads. B (hi|lo, 139264 B) resident in SMEM.
// A in 4 resident slots of 18432 B: slot0=Ahi.ch0 slot1=Ahi.ch1
// slot2=Alo.ch0 slot3=Alo.ch1 — each chunk fetched exactly once per tile.
// Iterations (p,ch): (0,0)(0,1)(1,0)(1,1)(2,0)(2,1) -> slots 0,1,0,1,2,3;
// its 2,3 reuse resident data (no wait, no sync).
#define SM_B    0u
#define SM_A    139264u
#define A_SLOT  18432u
#define GEMM_SMEM 212992

// fetch one A chunk (rows row0.., source As, k-half ch) into slot
__device__ __forceinline__ void fetch_a(uint32_t sbase, int row0, const char* As,
                                        int ch, int slot, int tid) {
#pragma unroll
    for (int j = 0; j < 2; j++) {
        int i = tid + j * 512;          // 1024 16B chunks
        int r = i >> 3;                 // 8 chunks per 128B row
        int q = i & 7;
        int gr = row0 + r;
        if (gr >= NN) gr = NN - 1;      // clamped rows discarded in epilogue
        CP_ASYNC16(sbase + SM_A + (uint32_t)(slot * (int)A_SLOT + r * 144 + q * 16),
                   As + (size_t)gr * 256 + ch * 128 + q * 16);
    }
}

__global__ void __launch_bounds__(512, 1)
gemm_tc(const float* __restrict__ att_src,
        const float* __restrict__ att_dst,
        float* __restrict__ out)
{
    extern __shared__ unsigned char smem[];
    const uint32_t sbase = smem_u32(smem);
    const int tid = threadIdx.x;
    const char* Ahi = (const char*)g_Ahi;
    const char* Alo = (const char*)g_Alo;

    // ---- load resident B once (group 1) ----
    {
        const char* bs = (const char*)g_Bpk;
#pragma unroll
        for (int j = 0; j < 17; j++) {
            uint32_t off = (uint32_t)(tid + j * 512) * 16;
            CP_ASYNC16(sbase + SM_B + off, bs + off);
        }
        CP_COMMIT();
    }

    const int lane = tid & 31;
    const int wid = tid >> 5;
    const int wm = wid & 3;        // 4 m-tiles of 32 rows
    const int wn = wid >> 2;       // 4 n-tiles of 64 cols

    const uint32_t aRow = (uint32_t)(wm * 32 + (lane & 15));
    const uint32_t aKb  = (uint32_t)((lane >> 4) * 16);
    const uint32_t bN   = (uint32_t)(wn * 64 + ((lane >> 4) * 8) + (lane & 7));
    const uint32_t bKb  = (uint32_t)(((lane >> 3) & 1) * 16);
    const int qlane = lane >> 2;
    const int qcol  = (lane & 3) * 2;

    // prologue: this tile's two Ahi chunks (groups 2, 3)
    int tile = blockIdx.x;
    fetch_a(sbase, tile * 128, Ahi, 0, 0, tid);
    CP_COMMIT();
    fetch_a(sbase, tile * 128, Ahi, 1, 1, tid);
    CP_COMMIT();

    for (; tile < NTILES; tile += NCTA) {
        const int row0 = tile * 128;
        const int ntile = tile + NCTA;

        float c[2][8][4];
#pragma unroll
        for (int mi = 0; mi < 2; mi++)
#pragma unroll
            for (int ni = 0; ni < 8; ni++)
#pragma unroll
                for (int q = 0; q < 4; q++) c[mi][ni][q] = 0.f;

#pragma unroll
        for (int it = 0; it < 6; it++) {
            const int p = it >> 1, ch = it & 1;
            const int slot = (p == 2) ? (2 + ch) : ch;

            // waits/syncs/prefetches only where new data arrives
            if (it == 0) {
                CP_WAIT1(); __syncthreads();
                fetch_a(sbase, row0, Alo, 0, 2, tid);   // -> slot2
                CP_COMMIT();
            } else if (it == 1) {
                CP_WAIT1(); __syncthreads();
                fetch_a(sbase, row0, Alo, 1, 3, tid);   // -> slot3
                CP_COMMIT();
            } else if (it == 4) {
                CP_WAIT1(); __syncthreads();
                if (ntile < NTILES)
                    fetch_a(sbase, ntile * 128, Ahi, 0, 0, tid);  // -> slot0
                CP_COMMIT();
            } else if (it == 5) {
                CP_WAIT1(); __syncthreads();
                if (ntile < NTILES)
                    fetch_a(sbase, ntile * 128, Ahi, 1, 1, tid);  // -> slot1
                CP_COMMIT();
            }
            // its 2,3: slots 0,1 already resident — no wait, no sync

            const uint32_t aAddr0 = sbase + SM_A + (uint32_t)slot * A_SLOT +
                                    aRow * 144 + aKb;
            const uint32_t bAddr0 = sbase + SM_B + (p == 1 ? 69632u : 0u) +
                                    bN * 272 + (uint32_t)(ch * 128) + bKb;
#pragma unroll
            for (int ks = 0; ks < 4; ks++) {
                const uint32_t kb = (uint32_t)(ks * 32);
                uint32_t a[2][4];
                LDSM4(a[0][0], a[0][1], a[0][2], a[0][3], aAddr0 + kb);
                LDSM4(a[1][0], a[1][1], a[1][2], a[1][3], aAddr0 + 16 * 144 + kb);
                uint32_t b[8][2];
#pragma unroll
                for (int nj = 0; nj < 4; nj++) {
                    LDSM4(b[2 * nj][0], b[2 * nj][1], b[2 * nj + 1][0], b[2 * nj + 1][1],
                          bAddr0 + (uint32_t)(nj * 16 * 272) + kb);
                }
#pragma unroll
                for (int mi = 0; mi < 2; mi++)
#pragma unroll
                    for (int ni = 0; ni < 8; ni++)
                        MMA16816(c[mi][ni], a[mi], b[ni]);
            }
        }

        // ---- epilogue (registers only) ----
#pragma unroll
        for (int mi = 0; mi < 2; mi++) {
            const int rA = row0 + wm * 32 + mi * 16 + qlane;
            const int rB = rA + 8;
#pragma unroll
            for (int ni = 0; ni < 8; ni++) {
                const int col = wn * 64 + ni * 8 + qcol;
                if (col < 128) {
                    __half2 pA = __float22half2_rn(make_float2(c[mi][ni][0], c[mi][ni][1]));
                    __half2 pB = __float22half2_rn(make_float2(c[mi][ni][2], c[mi][ni][3]));
                    if (rA < NN) *(__half2*)(g_xh + (size_t)rA * 128 + col) = pA;
                    if (rB < NN) *(__half2*)(g_xh + (size_t)rB * 128 + col) = pB;
                } else {
                    if (rA < NN) *(float2*)(out + (size_t)rA * 128 + col - 128) =
                        make_float2(c[mi][ni][0], c[mi][ni][1]);
                    if (rB < NN) *(float2*)(out + (size_t)rB * 128 + col - 128) =
                        make_float2(c[mi][ni][2], c[mi][ni][3]);
                }
            }
        }

        // fused attention logits for the x half (wn 0,1), fp32-exact
        if (wn < 2) {
            const int hA = wn * 2;
            const int hB = wn * 2 + 1;
#pragma unroll
            for (int mi = 0; mi < 2; mi++) {
#pragma unroll
                for (int rp = 0; rp < 2; rp++) {
                    float sa = 0.f, da = 0.f, sb = 0.f, db = 0.f;
#pragma unroll
                    for (int ni = 0; ni < 4; ni++) {
                        const int col = wn * 64 + ni * 8 + qcol;
                        float x0 = c[mi][ni][2 * rp], x1 = c[mi][ni][2 * rp + 1];
                        sa = fmaf(x0, __ldg(att_src + col), sa);
                        sa = fmaf(x1, __ldg(att_src + col + 1), sa);
                        da = fmaf(x0, __ldg(att_dst + col), da);
                        da = fmaf(x1, __ldg(att_dst + col + 1), da);
                    }
#pragma unroll
                    for (int ni = 4; ni < 8; ni++) {
                        const int col = wn * 64 + ni * 8 + qcol;
                        float x0 = c[mi][ni][2 * rp], x1 = c[mi][ni][2 * rp + 1];
                        sb = fmaf(x0, __ldg(att_src + col), sb);
                        sb = fmaf(x1, __ldg(att_src + col + 1), sb);
                        db = fmaf(x0, __ldg(att_dst + col), db);
                        db = fmaf(x1, __ldg(att_dst + col + 1), db);
                    }
                    sa += __shfl_xor_sync(0xffffffffu, sa, 1);
                    sa += __shfl_xor_sync(0xffffffffu, sa, 2);
                    da += __shfl_xor_sync(0xffffffffu, da, 1);
                    da += __shfl_xor_sync(0xffffffffu, da, 2);
                    sb += __shfl_xor_sync(0xffffffffu, sb, 1);
                    sb += __shfl_xor_sync(0xffffffffu, sb, 2);
                    db += __shfl_xor_sync(0xffffffffu, db, 1);
                    db += __shfl_xor_sync(0xffffffffu, db, 2);
                    if ((lane & 3) == 0) {
                        const int r = row0 + wm * 32 + mi * 16 + rp * 8 + qlane;
                        if (r < NN) {
                            g_as[r * NH + hA] = sa;
                            g_ad[r * NH + hA] = da;
                            g_as[r * NH + hB] = sb;
                            g_ad[r * NH + hB] = db;
                        }
                    }
                }
            }
        }
    }
}

// ---------------- CSR build ----------------
__global__ void zero_cnt_kernel() {
    int i = blockIdx.x * blockDim.x + threadIdx.x;
    if (i < NN) g_cnt[i] = 0;
    if (i == 0) g_total = 0;
}

__global__ void hist_kernel(const int* __restrict__ dst) {
    int e = blockIdx.x * blockDim.x + threadIdx.x;
    if (e < NE) atomicAdd(&g_cnt[dst[e]], 1);
}

__global__ void alloc_kernel() {
    int i = blockIdx.x * blockDim.x + threadIdx.x;
    if (i >= NN) return;
    int c = g_cnt[i];
    int r = atomicAdd(&g_total, c);
    g_rowptr[i] = r;
    g_cursor[i] = r;
}

__global__ void scatter_kernel(const int* __restrict__ src,
                               const int* __restrict__ dst) {
    int e = blockIdx.x * blockDim.x + threadIdx.x;
    if (e >= NE) return;
    int d = dst[e];
    int pos = atomicAdd(&g_cursor[d], 1);
    g_csr_src[pos] = src[e];
}

// ---------------- node aggregation: half-warp per edge, 2-wide, single pass ----------------
__global__ void __launch_bounds__(256)
node_agg_kernel(float* __restrict__ out)
{
    int d = (blockIdx.x * blockDim.x + threadIdx.x) >> 5;
    int lane = threadIdx.x & 31;
    if (d >= NN) return;
    const int n = g_cnt[d];
    if (n == 0) return;   // out already holds the residual
    const int base = g_rowptr[d];

    const int half = lane >> 4;
    const int l16  = lane & 15;
    const int h    = l16 >> 2;
    const float adh = g_ad[(size_t)d * NH + h];

    float acc[8];
#pragma unroll
    for (int q = 0; q < 8; q++) acc[q] = 0.f;
    float den = 0.f;

    const int* cs = g_csr_src + base;
    const __half* xb = g_xh + (size_t)l16 * 8;

    int i = half;
    for (; i + 2 < n; i += 4) {
        int s0 = cs[i], s1 = cs[i + 2];
        float a0 = g_as[(size_t)s0 * NH + h];
        float a1 = g_as[(size_t)s1 * NH + h];
        uint4 v0 = *(const uint4*)(xb + (size_t)s0 * 128);
        uint4 v1 = *(const uint4*)(xb + (size_t)s1 * 128);
        float p0 = __expf(lrelu(a0 + adh));
        float p1 = __expf(lrelu(a1 + adh));
        den += p0 + p1;
        const __half2* b0 = (const __half2*)&v0;
        const __half2* b1 = (const __half2*)&v1;
#pragma unroll
        for (int q = 0; q < 4; q++) {
            float2 f0 = __half22float2(b0[q]);
            float2 f1 = __half22float2(b1[q]);
            acc[2 * q]     = fmaf(f0.x, p0, acc[2 * q]);
            acc[2 * q + 1] = fmaf(f0.y, p0, acc[2 * q + 1]);
            acc[2 * q]     = fmaf(f1.x, p1, acc[2 * q]);
            acc[2 * q + 1] = fmaf(f1.y, p1, acc[2 * q + 1]);
        }
    }
    if (i < n) {
        int s0 = cs[i];
        float a0 = g_as[(size_t)s0 * NH + h];
        uint4 v0 = *(const uint4*)(xb + (size_t)s0 * 128);
        float p0 = __expf(lrelu(a0 + adh));
        den += p0;
        const __half2* b0 = (const __half2*)&v0;
#pragma unroll
        for (int q = 0; q < 4; q++) {
            float2 f0 = __half22float2(b0[q]);
            acc[2 * q]     = fmaf(f0.x, p0, acc[2 * q]);
            acc[2 * q + 1] = fmaf(f0.y, p0, acc[2 * q + 1]);
        }
    }

#pragma unroll
    for (int q = 0; q < 8; q++)
        acc[q] += __shfl_xor_sync(0xffffffffu, acc[q], 16);
    den += __shfl_xor_sync(0xffffffffu, den, 16);

    if (half == 0) {
        const float inv = 1.0f / den;
        float* o = out + (size_t)d * 128 + l16 * 8;
        float4 r0 = *(const float4*)o;
        float4 r1 = *(const float4*)(o + 4);
        r0.x = fmaf(acc[0], inv, r0.x);
        r0.y = fmaf(acc[1], inv, r0.y);
        r0.z = fmaf(acc[2], inv, r0.z);
        r0.w = fmaf(acc[3], inv, r0.w);
        r1.x = fmaf(acc[4], inv, r1.x);
        r1.y = fmaf(acc[5], inv, r1.y);
        r1.z = fmaf(acc[6], inv, r1.z);
        r1.w = fmaf(acc[7], inv, r1.w);
        *(float4*)o = r0;
        *(float4*)(o + 4) = r1;
    }
}

// ---------------- launch ----------------
extern "C" void kernel_launch(void* const* d_in, const int* in_sizes, int n_in,
                              void* d_out, int out_size)
{
    const float* feat    = (const float*)d_in[0];
    const float* W       = (const float*)d_in[1];
    const float* att_src = (const float*)d_in[2];
    const float* att_dst = (const float*)d_in[3];
    const float* Wres    = (const float*)d_in[4];
    const int*   src     = (const int*)d_in[5];
    const int*   dst     = (const int*)d_in[6];
    float* out = (float*)d_out;

    static cudaStream_t s2 = nullptr;
    static cudaEvent_t evFork = nullptr, evJoin = nullptr;
    if (!s2) {
        cudaFuncSetAttribute(gemm_tc,
                             cudaFuncAttributeMaxDynamicSharedMemorySize,
                             GEMM_SMEM);
        cudaStreamCreateWithFlags(&s2, cudaStreamNonBlocking);
        cudaEventCreateWithFlags(&evFork, cudaEventDisableTiming);
        cudaEventCreateWithFlags(&evJoin, cudaEventDisableTiming);
    }

    // fork: CSR build on s2, prep+GEMM on the main stream.
    // Enqueue order keeps gemm_tc 4th (profiler targeting).
    cudaEventRecord(evFork, 0);
    cudaStreamWaitEvent(s2, evFork, 0);

    zero_cnt_kernel<<<NB, 256, 0, s2>>>();                       // 1
    hist_kernel<<<(NE + 255) / 256, 256, 0, s2>>>(dst);          // 2
    prep_ab<<<16 + (NN * 16 + 255) / 256, 256>>>(W, Wres, feat); // 3
    gemm_tc<<<NCTA, 512, GEMM_SMEM>>>(att_src, att_dst, out);    // 4
    alloc_kernel<<<NB, 256, 0, s2>>>();                          // 5
    scatter_kernel<<<(NE + 255) / 256, 256, 0, s2>>>(src, dst);  // 6
    cudaEventRecord(evJoin, s2);

    // join: aggregation needs both GEMM outputs and the CSR
    cudaStreamWaitEvent(0, evJoin, 0);
    node_agg_kernel<<<(NN * 32 + 255) / 256, 256>>>(out);        // 7
}